// round 1
// baseline (speedup 1.0000x reference)
#include <cuda_runtime.h>
#include <math.h>

// Problem constants
#define Bsz 2
#define Nseq 4096
#define Emb 768
#define Hh 8
#define Dh 96
#define Mrows (Bsz * Nseq)          // 8192
#define DP 97                        // padded D for smem (odd -> conflict-free)
#define SP 65                        // padded 64 for S tile

// Scratch (no cudaMalloc allowed): Q,K,V in [B,H,N,D], attn out in [B,N,E]
__device__ float g_q[Bsz * Hh * Nseq * Dh];
__device__ float g_k[Bsz * Hh * Nseq * Dh];
__device__ float g_v[Bsz * Hh * Nseq * Dh];
__device__ float g_attn[Bsz * Nseq * Emb];

// ---------------------------------------------------------------------------
// Tiled SGEMM: C[M,768] = A[M,768] @ W[768,768] + bias
// mode 0: store plain row-major [M,768]
// mode 1: store to [B,H,N,D] layout (split heads)
// Tiles: 64x64, K-tile 16, 256 threads, 4x4 per-thread microtile.
// ---------------------------------------------------------------------------
__global__ void gemm64_kernel(const float* __restrict__ A,
                              const float* __restrict__ W,
                              const float* __restrict__ bias,
                              float* __restrict__ C, int mode)
{
    const int K = Emb, NC = Emb;
    __shared__ float As[64][17];  // [row][k], padded
    __shared__ float Ws[16][65];  // [k][col], padded

    int tid = threadIdx.x;
    int tx = tid & 15;
    int ty = tid >> 4;
    int row0 = blockIdx.y * 64;
    int col0 = blockIdx.x * 64;

    float acc[4][4];
#pragma unroll
    for (int i = 0; i < 4; i++)
#pragma unroll
        for (int j = 0; j < 4; j++) acc[i][j] = 0.f;

    for (int k0 = 0; k0 < K; k0 += 16) {
        // load A tile 64x16 (4 elems/thread)
#pragma unroll
        for (int i = 0; i < 4; i++) {
            int idx = tid + i * 256;
            int r = idx >> 4, c = idx & 15;
            As[r][c] = A[(row0 + r) * K + k0 + c];
        }
        // load W tile 16x64 (4 elems/thread)
#pragma unroll
        for (int i = 0; i < 4; i++) {
            int idx = tid + i * 256;
            int r = idx >> 6, c = idx & 63;
            Ws[r][c] = W[(k0 + r) * NC + col0 + c];
        }
        __syncthreads();
#pragma unroll
        for (int k = 0; k < 16; k++) {
            float a[4], b[4];
#pragma unroll
            for (int i = 0; i < 4; i++) a[i] = As[ty * 4 + i][k];
#pragma unroll
            for (int j = 0; j < 4; j++) b[j] = Ws[k][tx * 4 + j];
#pragma unroll
            for (int i = 0; i < 4; i++)
#pragma unroll
                for (int j = 0; j < 4; j++) acc[i][j] += a[i] * b[j];
        }
        __syncthreads();
    }

#pragma unroll
    for (int i = 0; i < 4; i++) {
#pragma unroll
        for (int j = 0; j < 4; j++) {
            int r = row0 + ty * 4 + i;
            int c = col0 + tx * 4 + j;
            float v = acc[i][j] + bias[c];
            if (mode == 0) {
                C[r * NC + c] = v;
            } else {
                int b = r >> 12;          // r / 4096
                int n = r & 4095;         // r % 4096
                int h = c / Dh;
                int d = c - h * Dh;
                C[((b * Hh + h) * Nseq + n) * Dh + d] = v;
            }
        }
    }
}

// ---------------------------------------------------------------------------
// Flash attention, fp32. One CTA = 64 queries of one (b,h). Streams K in
// 64-row tiles. Online softmax. NOTE: reference divides by sqrt(D) AFTER
// softmax, so we just scale the final output by 1/sqrt(96).
// Dynamic smem: 4*64*97 + 64*65 + 128 floats = 116480 bytes.
// ---------------------------------------------------------------------------
__global__ void attn_kernel(const float* __restrict__ Q,
                            const float* __restrict__ K,
                            const float* __restrict__ V,
                            float* __restrict__ O)
{
    extern __shared__ float sm[];
    float* sQ  = sm;                 // 64*DP
    float* sK  = sQ + 64 * DP;       // 64*DP
    float* sV  = sK + 64 * DP;       // 64*DP
    float* sO  = sV + 64 * DP;       // 64*DP
    float* sS  = sO + 64 * DP;       // 64*SP
    float* sMx = sS + 64 * SP;       // 64
    float* sL  = sMx + 64;           // 64

    int bh  = blockIdx.y;            // b*H + h
    int q0  = blockIdx.x * 64;
    int tid = threadIdx.x;

    const float* Qb = Q + (bh * Nseq + q0) * Dh;

    // load Q tile; init O, m, l
    for (int idx = tid; idx < 64 * Dh; idx += 256) {
        int r = idx / Dh, d = idx - r * Dh;
        sQ[r * DP + d] = Qb[idx];
        sO[r * DP + d] = 0.f;
    }
    if (tid < 64) { sMx[tid] = -1e30f; sL[tid] = 0.f; }
    __syncthreads();

    for (int kt = 0; kt < Nseq; kt += 64) {
        const float* Kb = K + (bh * Nseq + kt) * Dh;
        const float* Vb = V + (bh * Nseq + kt) * Dh;
        for (int idx = tid; idx < 64 * Dh; idx += 256) {
            int r = idx / Dh, d = idx - r * Dh;
            sK[r * DP + d] = Kb[idx];
            sV[r * DP + d] = Vb[idx];
        }
        __syncthreads();

        // S = Q @ K^T : 16x16 threads, 4x4 microtile
        {
            int tx = tid & 15, ty = tid >> 4;
            float acc[4][4];
#pragma unroll
            for (int i = 0; i < 4; i++)
#pragma unroll
                for (int j = 0; j < 4; j++) acc[i][j] = 0.f;
            for (int d = 0; d < Dh; d++) {
                float a[4], b[4];
#pragma unroll
                for (int i = 0; i < 4; i++) a[i] = sQ[(ty * 4 + i) * DP + d];
#pragma unroll
                for (int j = 0; j < 4; j++) b[j] = sK[(tx * 4 + j) * DP + d];
#pragma unroll
                for (int i = 0; i < 4; i++)
#pragma unroll
                    for (int j = 0; j < 4; j++) acc[i][j] += a[i] * b[j];
            }
#pragma unroll
            for (int i = 0; i < 4; i++)
#pragma unroll
                for (int j = 0; j < 4; j++)
                    sS[(ty * 4 + i) * SP + tx * 4 + j] = acc[i][j];
        }
        __syncthreads();

        // online softmax: warp w owns rows [w*8, w*8+8)
        {
            int w = tid >> 5, lane = tid & 31;
            for (int rr = 0; rr < 8; rr++) {
                int r = w * 8 + rr;
                float s0 = sS[r * SP + lane];
                float s1 = sS[r * SP + lane + 32];
                float m = fmaxf(s0, s1);
#pragma unroll
                for (int off = 16; off; off >>= 1)
                    m = fmaxf(m, __shfl_xor_sync(0xffffffffu, m, off));
                float oldM = sMx[r];
                float newM = fmaxf(oldM, m);
                float p0 = expf(s0 - newM);
                float p1 = expf(s1 - newM);
                sS[r * SP + lane] = p0;
                sS[r * SP + lane + 32] = p1;
                float rs = p0 + p1;
#pragma unroll
                for (int off = 16; off; off >>= 1)
                    rs += __shfl_xor_sync(0xffffffffu, rs, off);
                float scale = expf(oldM - newM);
                if (lane == 0) {
                    sMx[r] = newM;
                    sL[r] = sL[r] * scale + rs;
                }
                // rescale accumulator row
                for (int d = lane; d < Dh; d += 32)
                    sO[r * DP + d] *= scale;
            }
        }
        __syncthreads();

        // O += P @ V : 16 row-groups x 16 d-groups, 4 rows x 6 d per thread
        {
            int ty = tid >> 4;          // row group
            int tx = tid & 15;          // d group
            int d0 = tx * 6;
            float acc[4][6];
#pragma unroll
            for (int i = 0; i < 4; i++)
#pragma unroll
                for (int j = 0; j < 6; j++)
                    acc[i][j] = sO[(ty * 4 + i) * DP + d0 + j];
            for (int k = 0; k < 64; k++) {
                float p[4], v[6];
#pragma unroll
                for (int i = 0; i < 4; i++) p[i] = sS[(ty * 4 + i) * SP + k];
#pragma unroll
                for (int j = 0; j < 6; j++) v[j] = sV[k * DP + d0 + j];
#pragma unroll
                for (int i = 0; i < 4; i++)
#pragma unroll
                    for (int j = 0; j < 6; j++) acc[i][j] += p[i] * v[j];
            }
#pragma unroll
            for (int i = 0; i < 4; i++)
#pragma unroll
                for (int j = 0; j < 6; j++)
                    sO[(ty * 4 + i) * DP + d0 + j] = acc[i][j];
        }
        __syncthreads();
    }

    // epilogue: out = O / l / sqrt(D), merged-head layout [B,N,E]
    int b = bh >> 3, h = bh & 7;
    const float inv_scaling = 0.1020620726159657f;  // 1/sqrt(96)
    for (int idx = tid; idx < 64 * Dh; idx += 256) {
        int r = idx / Dh, d = idx - r * Dh;
        float v = sO[r * DP + d] * (inv_scaling / sL[r]);
        O[(b * Nseq + q0 + r) * Emb + h * Dh + d] = v;
    }
}

// ---------------------------------------------------------------------------
// Launch
// ---------------------------------------------------------------------------
extern "C" void kernel_launch(void* const* d_in, const int* in_sizes, int n_in,
                              void* d_out, int out_size)
{
    const float* x  = (const float*)d_in[0];
    const float* Wq = (const float*)d_in[1];
    const float* bq = (const float*)d_in[2];
    const float* Wk = (const float*)d_in[3];
    const float* bk = (const float*)d_in[4];
    const float* Wv = (const float*)d_in[5];
    const float* bv = (const float*)d_in[6];
    const float* Wo = (const float*)d_in[7];
    const float* bo = (const float*)d_in[8];
    float* out = (float*)d_out;

    float *q, *k, *v, *attn;
    cudaGetSymbolAddress((void**)&q, g_q);
    cudaGetSymbolAddress((void**)&k, g_k);
    cudaGetSymbolAddress((void**)&v, g_v);
    cudaGetSymbolAddress((void**)&attn, g_attn);

    const int ATTN_SMEM = (4 * 64 * DP + 64 * SP + 128) * (int)sizeof(float);
    cudaFuncSetAttribute(attn_kernel,
                         cudaFuncAttributeMaxDynamicSharedMemorySize, ATTN_SMEM);

    dim3 gg(Emb / 64, Mrows / 64);   // (12, 128)
    dim3 gt(256);

    gemm64_kernel<<<gg, gt>>>(x, Wq, bq, q, 1);
    gemm64_kernel<<<gg, gt>>>(x, Wk, bk, k, 1);
    gemm64_kernel<<<gg, gt>>>(x, Wv, bv, v, 1);

    dim3 ag(Nseq / 64, Bsz * Hh);    // (64, 16)
    attn_kernel<<<ag, 256, ATTN_SMEM>>>(q, k, v, attn);

    gemm64_kernel<<<gg, gt>>>(attn, Wo, bo, out, 0);
}

// round 2
// speedup vs baseline: 3.1676x; 3.1676x over previous
#include <cuda_runtime.h>
#include <cuda_bf16.h>
#include <stdint.h>
#include <math.h>

// ---------------------------------------------------------------------------
// Problem: B=2, N=4096, E=768, H=8, D=96.  Softmax divided by sqrt(D) AFTER.
// Strategy: split-bf16 (hi+lo) 3-MMA emulation of fp32 GEMM on tensor cores.
// ---------------------------------------------------------------------------
#define Mrows   8192
#define Emb     768
#define Nseq    4096
#define Hh      8
#define Dh      96
#define NBH     16

// ---------------- device scratch (no cudaMalloc allowed) -------------------
__device__ __align__(16) __nv_bfloat16 g_xh[Mrows * Emb];
__device__ __align__(16) __nv_bfloat16 g_xl[Mrows * Emb];
__device__ __align__(16) __nv_bfloat16 g_wh[4][Emb * Emb];   // W^T hi  [n][k]
__device__ __align__(16) __nv_bfloat16 g_wl[4][Emb * Emb];   // W^T lo
__device__ __align__(16) __nv_bfloat16 g_qh[NBH * Nseq * Dh];
__device__ __align__(16) __nv_bfloat16 g_ql[NBH * Nseq * Dh];
__device__ __align__(16) __nv_bfloat16 g_kh[NBH * Nseq * Dh];
__device__ __align__(16) __nv_bfloat16 g_kl[NBH * Nseq * Dh];
__device__ __align__(16) __nv_bfloat16 g_vh[NBH * Dh * Nseq]; // transposed [bh][d][n]
__device__ __align__(16) __nv_bfloat16 g_vl[NBH * Dh * Nseq];
__device__ __align__(16) __nv_bfloat16 g_ah[Mrows * Emb];     // attention out hi
__device__ __align__(16) __nv_bfloat16 g_al[Mrows * Emb];

// ---------------- helpers ---------------------------------------------------
__device__ __forceinline__ void mma_bf16(float* c, const uint32_t* a,
                                         uint32_t b0, uint32_t b1)
{
    asm volatile(
        "mma.sync.aligned.m16n8k16.row.col.f32.bf16.bf16.f32 "
        "{%0,%1,%2,%3}, {%4,%5,%6,%7}, {%8,%9}, {%0,%1,%2,%3};\n"
        : "+f"(c[0]), "+f"(c[1]), "+f"(c[2]), "+f"(c[3])
        : "r"(a[0]), "r"(a[1]), "r"(a[2]), "r"(a[3]), "r"(b0), "r"(b1));
}

// pack two fp32 -> bf16x2 (lo = first element, hi = second element)
__device__ __forceinline__ uint32_t pk(float lo, float hi)
{
    uint32_t r;
    asm("cvt.rn.bf16x2.f32 %0, %1, %2;" : "=r"(r) : "f"(hi), "f"(lo));
    return r;
}

__device__ __forceinline__ float rb(float x)
{
    return __bfloat162float(__float2bfloat16(x));
}

__device__ __forceinline__ void splitstore(__nv_bfloat16* H, __nv_bfloat16* L,
                                           size_t idx, float v)
{
    __nv_bfloat16 h = __float2bfloat16(v);
    H[idx] = h;
    L[idx] = __float2bfloat16(v - __bfloat162float(h));
}

// ---------------- conversion kernels ---------------------------------------
__global__ void conv_split_kernel(const float* __restrict__ X,
                                  __nv_bfloat16* __restrict__ H,
                                  __nv_bfloat16* __restrict__ L, int n)
{
    int i = blockIdx.x * 256 + threadIdx.x;
    if (i < n) {
        float v = X[i];
        __nv_bfloat16 h = __float2bfloat16(v);
        H[i] = h;
        L[i] = __float2bfloat16(v - __bfloat162float(h));
    }
}

// W [k][n] fp32 -> W^T hi/lo [n][k] bf16
__global__ void conv_w_kernel(const float* __restrict__ W,
                              __nv_bfloat16* __restrict__ H,
                              __nv_bfloat16* __restrict__ L)
{
    int i = blockIdx.x * 256 + threadIdx.x;
    if (i < Emb * Emb) {
        int k = i / Emb, n = i - k * Emb;
        float v = W[i];
        __nv_bfloat16 h = __float2bfloat16(v);
        size_t o = (size_t)n * Emb + k;
        H[o] = h;
        L[o] = __float2bfloat16(v - __bfloat162float(h));
    }
}

// ---------------- split-bf16 GEMM: C = A @ W + bias -------------------------
// A hi/lo [M][768] row-major, Wt hi/lo [n][k].  64x64 CTA tile, BK=16, 4 warps.
// mode 0: fp32 to Cf [M][768]
// mode 1: split-bf16 head-split  [bh][n][d]
// mode 2: split-bf16 transposed  [bh][d][n]
#define GSTR 24
__global__ __launch_bounds__(128) void gemm_mma_kernel(
    const __nv_bfloat16* __restrict__ Ah, const __nv_bfloat16* __restrict__ Al,
    const __nv_bfloat16* __restrict__ Bh, const __nv_bfloat16* __restrict__ Bl,
    const float* __restrict__ bias, int mode,
    float* __restrict__ Cf,
    __nv_bfloat16* __restrict__ Ch, __nv_bfloat16* __restrict__ Cl)
{
    __shared__ __nv_bfloat16 sA[2][64 * GSTR];
    __shared__ __nv_bfloat16 sB[2][64 * GSTR];

    const int tid = threadIdx.x;
    const int warp = tid >> 5, lane = tid & 31;
    const int g = lane >> 2, t = lane & 3;
    const int wm = warp >> 1, wn = warp & 1;
    const int row0 = blockIdx.y * 64, col0 = blockIdx.x * 64;

    float acc[2][4][4];
#pragma unroll
    for (int i = 0; i < 2; i++)
#pragma unroll
        for (int j = 0; j < 4; j++)
#pragma unroll
            for (int c = 0; c < 4; c++) acc[i][j][c] = 0.f;

    for (int k0 = 0; k0 < Emb; k0 += 16) {
        {
            int r = tid >> 1, c = tid & 1;
            *(uint4*)&sA[0][r * GSTR + c * 8] =
                *(const uint4*)(Ah + (size_t)(row0 + r) * Emb + k0 + c * 8);
            *(uint4*)&sA[1][r * GSTR + c * 8] =
                *(const uint4*)(Al + (size_t)(row0 + r) * Emb + k0 + c * 8);
            *(uint4*)&sB[0][r * GSTR + c * 8] =
                *(const uint4*)(Bh + (size_t)(col0 + r) * Emb + k0 + c * 8);
            *(uint4*)&sB[1][r * GSTR + c * 8] =
                *(const uint4*)(Bl + (size_t)(col0 + r) * Emb + k0 + c * 8);
        }
        __syncthreads();

        uint32_t ah[2][4], al2[2][4];
#pragma unroll
        for (int mb = 0; mb < 2; mb++) {
            int rr = wm * 32 + mb * 16 + g;
            int cc = 2 * t;
            ah[mb][0] = *(const uint32_t*)&sA[0][rr * GSTR + cc];
            ah[mb][1] = *(const uint32_t*)&sA[0][(rr + 8) * GSTR + cc];
            ah[mb][2] = *(const uint32_t*)&sA[0][rr * GSTR + cc + 8];
            ah[mb][3] = *(const uint32_t*)&sA[0][(rr + 8) * GSTR + cc + 8];
            al2[mb][0] = *(const uint32_t*)&sA[1][rr * GSTR + cc];
            al2[mb][1] = *(const uint32_t*)&sA[1][(rr + 8) * GSTR + cc];
            al2[mb][2] = *(const uint32_t*)&sA[1][rr * GSTR + cc + 8];
            al2[mb][3] = *(const uint32_t*)&sA[1][(rr + 8) * GSTR + cc + 8];
        }
#pragma unroll
        for (int nb = 0; nb < 4; nb++) {
            int cn = wn * 32 + nb * 8 + g;
            uint32_t bh0 = *(const uint32_t*)&sB[0][cn * GSTR + 2 * t];
            uint32_t bh1 = *(const uint32_t*)&sB[0][cn * GSTR + 8 + 2 * t];
            uint32_t bl0 = *(const uint32_t*)&sB[1][cn * GSTR + 2 * t];
            uint32_t bl1 = *(const uint32_t*)&sB[1][cn * GSTR + 8 + 2 * t];
#pragma unroll
            for (int mb = 0; mb < 2; mb++) {
                mma_bf16(acc[mb][nb], ah[mb], bh0, bh1);
                mma_bf16(acc[mb][nb], ah[mb], bl0, bl1);
                mma_bf16(acc[mb][nb], al2[mb], bh0, bh1);
            }
        }
        __syncthreads();
    }

    // epilogue
#pragma unroll
    for (int mb = 0; mb < 2; mb++) {
#pragma unroll
        for (int nb = 0; nb < 4; nb++) {
            int r = row0 + wm * 32 + mb * 16 + g;
            int cb = col0 + wn * 32 + nb * 8 + 2 * t;
#pragma unroll
            for (int c = 0; c < 4; c++) {
                int rr = r + (c >= 2 ? 8 : 0);
                int cc = cb + (c & 1);
                float v = acc[mb][nb][c] + bias[cc];
                if (mode == 0) {
                    Cf[(size_t)rr * Emb + cc] = v;
                } else {
                    int b = rr >> 12, n = rr & 4095;
                    int h = cc / Dh, d = cc - h * Dh;
                    size_t idx;
                    if (mode == 1)
                        idx = ((size_t)(b * Hh + h) * Nseq + n) * Dh + d;
                    else
                        idx = ((size_t)(b * Hh + h) * Dh + d) * Nseq + n;
                    splitstore(Ch, Cl, idx, v);
                }
            }
        }
    }
}

// ---------------- flash attention with split-bf16 MMA ----------------------
#define QS 120
#define VS 88
#define OFF_QH 0
#define OFF_QL (64 * QS * 2)
#define OFF_KH (2 * 64 * QS * 2)
#define OFF_KL (3 * 64 * QS * 2)
#define OFF_VH (4 * 64 * QS * 2)
#define OFF_VL (4 * 64 * QS * 2 + 96 * VS * 2)
#define ATTN_SMEM (4 * 64 * QS * 2 + 2 * 96 * VS * 2)   // 95232 bytes

__global__ __launch_bounds__(128) void attn_mma_kernel(
    const __nv_bfloat16* __restrict__ Qh, const __nv_bfloat16* __restrict__ Ql,
    const __nv_bfloat16* __restrict__ Kh, const __nv_bfloat16* __restrict__ Kl,
    const __nv_bfloat16* __restrict__ Vh, const __nv_bfloat16* __restrict__ Vl,
    __nv_bfloat16* __restrict__ Oh, __nv_bfloat16* __restrict__ Ol)
{
    extern __shared__ char sm[];
    const int tid = threadIdx.x;
    const int warp = tid >> 5, lane = tid & 31;
    const int g = lane >> 2, t = lane & 3;
    const int bh = blockIdx.y;
    const int q0 = blockIdx.x * 64;

    // --- load Q tile (hi/lo) into smem
    {
        const uint4* gQh = (const uint4*)(Qh + ((size_t)bh * Nseq + q0) * Dh);
        const uint4* gQl = (const uint4*)(Ql + ((size_t)bh * Nseq + q0) * Dh);
        for (int i = tid; i < 768; i += 128) {
            int r = i / 12, c = i - r * 12;
            *(uint4*)(sm + OFF_QH + r * 240 + c * 16) = gQh[r * 12 + c];
            *(uint4*)(sm + OFF_QL + r * 240 + c * 16) = gQl[r * 12 + c];
        }
    }
    __syncthreads();

    // --- Q fragments (register resident for the whole CTA lifetime)
    uint32_t qh[6][4], ql[6][4];
    {
        const __nv_bfloat16* sQh = (const __nv_bfloat16*)(sm + OFF_QH);
        const __nv_bfloat16* sQl = (const __nv_bfloat16*)(sm + OFF_QL);
        int r0 = warp * 16 + g;
#pragma unroll
        for (int kb = 0; kb < 6; kb++) {
            int c0 = kb * 16 + 2 * t;
            qh[kb][0] = *(const uint32_t*)(sQh + r0 * QS + c0);
            qh[kb][1] = *(const uint32_t*)(sQh + (r0 + 8) * QS + c0);
            qh[kb][2] = *(const uint32_t*)(sQh + r0 * QS + c0 + 8);
            qh[kb][3] = *(const uint32_t*)(sQh + (r0 + 8) * QS + c0 + 8);
            ql[kb][0] = *(const uint32_t*)(sQl + r0 * QS + c0);
            ql[kb][1] = *(const uint32_t*)(sQl + (r0 + 8) * QS + c0);
            ql[kb][2] = *(const uint32_t*)(sQl + r0 * QS + c0 + 8);
            ql[kb][3] = *(const uint32_t*)(sQl + (r0 + 8) * QS + c0 + 8);
        }
    }

    float o[12][4];
#pragma unroll
    for (int i = 0; i < 12; i++)
#pragma unroll
        for (int c = 0; c < 4; c++) o[i][c] = 0.f;
    float m0 = -1e30f, m1 = -1e30f, l0 = 0.f, l1 = 0.f;

    const __nv_bfloat16* sKh = (const __nv_bfloat16*)(sm + OFF_KH);
    const __nv_bfloat16* sKl = (const __nv_bfloat16*)(sm + OFF_KL);
    const __nv_bfloat16* sVh = (const __nv_bfloat16*)(sm + OFF_VH);
    const __nv_bfloat16* sVl = (const __nv_bfloat16*)(sm + OFF_VL);

    for (int kt = 0; kt < 64; kt++) {
        // --- stage K (hi/lo) and V^T (hi/lo) tiles
        {
            const uint4* gKh = (const uint4*)(Kh + ((size_t)bh * Nseq + kt * 64) * Dh);
            const uint4* gKl = (const uint4*)(Kl + ((size_t)bh * Nseq + kt * 64) * Dh);
            const uint4* gVh = (const uint4*)(Vh + (size_t)bh * Dh * Nseq + kt * 64);
            const uint4* gVl = (const uint4*)(Vl + (size_t)bh * Dh * Nseq + kt * 64);
            for (int i = tid; i < 768; i += 128) {
                int r = i / 12, c = i - r * 12;
                *(uint4*)(sm + OFF_KH + r * 240 + c * 16) = gKh[r * 12 + c];
                *(uint4*)(sm + OFF_KL + r * 240 + c * 16) = gKl[r * 12 + c];
                int rv = i >> 3, cv = i & 7;
                *(uint4*)(sm + OFF_VH + rv * 176 + cv * 16) = gVh[(size_t)rv * 512 + cv];
                *(uint4*)(sm + OFF_VL + rv * 176 + cv * 16) = gVl[(size_t)rv * 512 + cv];
            }
        }
        __syncthreads();

        // --- S = Q K^T (3-term split)
        float s[8][4];
#pragma unroll
        for (int nb = 0; nb < 8; nb++)
#pragma unroll
            for (int c = 0; c < 4; c++) s[nb][c] = 0.f;

#pragma unroll
        for (int kb = 0; kb < 6; kb++) {
#pragma unroll
            for (int nb = 0; nb < 8; nb++) {
                const __nv_bfloat16* kr = sKh + (nb * 8 + g) * QS + kb * 16 + 2 * t;
                const __nv_bfloat16* krl = sKl + (nb * 8 + g) * QS + kb * 16 + 2 * t;
                uint32_t bh0 = *(const uint32_t*)kr;
                uint32_t bh1 = *(const uint32_t*)(kr + 8);
                uint32_t bl0 = *(const uint32_t*)krl;
                uint32_t bl1 = *(const uint32_t*)(krl + 8);
                mma_bf16(s[nb], qh[kb], bh0, bh1);
                mma_bf16(s[nb], qh[kb], bl0, bl1);
                mma_bf16(s[nb], ql[kb], bh0, bh1);
            }
        }

        // --- online softmax (rows r0 = c0/c1, r1 = c2/c3)
        float mx0 = -1e30f, mx1 = -1e30f;
#pragma unroll
        for (int nb = 0; nb < 8; nb++) {
            mx0 = fmaxf(mx0, fmaxf(s[nb][0], s[nb][1]));
            mx1 = fmaxf(mx1, fmaxf(s[nb][2], s[nb][3]));
        }
        mx0 = fmaxf(mx0, __shfl_xor_sync(0xffffffffu, mx0, 1));
        mx0 = fmaxf(mx0, __shfl_xor_sync(0xffffffffu, mx0, 2));
        mx1 = fmaxf(mx1, __shfl_xor_sync(0xffffffffu, mx1, 1));
        mx1 = fmaxf(mx1, __shfl_xor_sync(0xffffffffu, mx1, 2));

        float nm0 = fmaxf(m0, mx0), nm1 = fmaxf(m1, mx1);
        float sc0 = __expf(m0 - nm0), sc1 = __expf(m1 - nm1);
        float rs0 = 0.f, rs1 = 0.f;
#pragma unroll
        for (int nb = 0; nb < 8; nb++) {
            s[nb][0] = __expf(s[nb][0] - nm0);
            s[nb][1] = __expf(s[nb][1] - nm0);
            s[nb][2] = __expf(s[nb][2] - nm1);
            s[nb][3] = __expf(s[nb][3] - nm1);
            rs0 += s[nb][0] + s[nb][1];
            rs1 += s[nb][2] + s[nb][3];
        }
        rs0 += __shfl_xor_sync(0xffffffffu, rs0, 1);
        rs0 += __shfl_xor_sync(0xffffffffu, rs0, 2);
        rs1 += __shfl_xor_sync(0xffffffffu, rs1, 1);
        rs1 += __shfl_xor_sync(0xffffffffu, rs1, 2);
        l0 = l0 * sc0 + rs0;
        l1 = l1 * sc1 + rs1;
        m0 = nm0;
        m1 = nm1;
#pragma unroll
        for (int nbd = 0; nbd < 12; nbd++) {
            o[nbd][0] *= sc0;
            o[nbd][1] *= sc0;
            o[nbd][2] *= sc1;
            o[nbd][3] *= sc1;
        }

        // --- O += P V (3-term split); kb outer keeps P frags small
#pragma unroll
        for (int kb = 0; kb < 4; kb++) {
            float a0 = s[2 * kb][0], a1 = s[2 * kb][1];
            float a2 = s[2 * kb][2], a3 = s[2 * kb][3];
            float b0 = s[2 * kb + 1][0], b1 = s[2 * kb + 1][1];
            float b2 = s[2 * kb + 1][2], b3 = s[2 * kb + 1][3];
            uint32_t PH[4], PL[4];
            PH[0] = pk(a0, a1); PH[1] = pk(a2, a3);
            PH[2] = pk(b0, b1); PH[3] = pk(b2, b3);
            PL[0] = pk(a0 - rb(a0), a1 - rb(a1));
            PL[1] = pk(a2 - rb(a2), a3 - rb(a3));
            PL[2] = pk(b0 - rb(b0), b1 - rb(b1));
            PL[3] = pk(b2 - rb(b2), b3 - rb(b3));
#pragma unroll
            for (int nbd = 0; nbd < 12; nbd++) {
                const __nv_bfloat16* vr = sVh + (nbd * 8 + g) * VS + kb * 16 + 2 * t;
                const __nv_bfloat16* vrl = sVl + (nbd * 8 + g) * VS + kb * 16 + 2 * t;
                uint32_t vh0 = *(const uint32_t*)vr;
                uint32_t vh1 = *(const uint32_t*)(vr + 8);
                uint32_t vl0 = *(const uint32_t*)vrl;
                uint32_t vl1 = *(const uint32_t*)(vrl + 8);
                mma_bf16(o[nbd], PH, vh0, vh1);
                mma_bf16(o[nbd], PH, vl0, vl1);
                mma_bf16(o[nbd], PL, vh0, vh1);
            }
        }
        __syncthreads();
    }

    // --- epilogue: normalize, post-softmax 1/sqrt(D), write split bf16 [B,N,E]
    const float isq = 0.1020620726159657f;   // 1/sqrt(96)
    float iv0 = isq / l0, iv1 = isq / l1;
    int b = bh >> 3, h = bh & 7;
    int r0 = q0 + warp * 16 + g;
    size_t row0 = (size_t)b * Nseq + r0;
    size_t row1 = row0 + 8;
#pragma unroll
    for (int nbd = 0; nbd < 12; nbd++) {
        int e = h * Dh + nbd * 8 + 2 * t;
        splitstore(Oh, Ol, row0 * Emb + e, o[nbd][0] * iv0);
        splitstore(Oh, Ol, row0 * Emb + e + 1, o[nbd][1] * iv0);
        splitstore(Oh, Ol, row1 * Emb + e, o[nbd][2] * iv1);
        splitstore(Oh, Ol, row1 * Emb + e + 1, o[nbd][3] * iv1);
    }
}

// ---------------------------------------------------------------------------
extern "C" void kernel_launch(void* const* d_in, const int* in_sizes, int n_in,
                              void* d_out, int out_size)
{
    const float* x  = (const float*)d_in[0];
    const float* Wq = (const float*)d_in[1];
    const float* bq = (const float*)d_in[2];
    const float* Wk = (const float*)d_in[3];
    const float* bk = (const float*)d_in[4];
    const float* Wv = (const float*)d_in[5];
    const float* bv = (const float*)d_in[6];
    const float* Wo = (const float*)d_in[7];
    const float* bo = (const float*)d_in[8];
    float* out = (float*)d_out;

    __nv_bfloat16 *xh, *xl, *wh, *wl, *qh, *ql, *kh, *kl, *vh, *vl, *ah, *al;
    cudaGetSymbolAddress((void**)&xh, g_xh);
    cudaGetSymbolAddress((void**)&xl, g_xl);
    cudaGetSymbolAddress((void**)&wh, g_wh);
    cudaGetSymbolAddress((void**)&wl, g_wl);
    cudaGetSymbolAddress((void**)&qh, g_qh);
    cudaGetSymbolAddress((void**)&ql, g_ql);
    cudaGetSymbolAddress((void**)&kh, g_kh);
    cudaGetSymbolAddress((void**)&kl, g_kl);
    cudaGetSymbolAddress((void**)&vh, g_vh);
    cudaGetSymbolAddress((void**)&vl, g_vl);
    cudaGetSymbolAddress((void**)&ah, g_ah);
    cudaGetSymbolAddress((void**)&al, g_al);

    cudaFuncSetAttribute(attn_mma_kernel,
                         cudaFuncAttributeMaxDynamicSharedMemorySize, ATTN_SMEM);

    // conversions
    conv_split_kernel<<<(Mrows * Emb + 255) / 256, 256>>>(x, xh, xl, Mrows * Emb);
    const int wgrid = (Emb * Emb + 255) / 256;
    conv_w_kernel<<<wgrid, 256>>>(Wq, wh + 0 * (size_t)Emb * Emb, wl + 0 * (size_t)Emb * Emb);
    conv_w_kernel<<<wgrid, 256>>>(Wk, wh + 1 * (size_t)Emb * Emb, wl + 1 * (size_t)Emb * Emb);
    conv_w_kernel<<<wgrid, 256>>>(Wv, wh + 2 * (size_t)Emb * Emb, wl + 2 * (size_t)Emb * Emb);
    conv_w_kernel<<<wgrid, 256>>>(Wo, wh + 3 * (size_t)Emb * Emb, wl + 3 * (size_t)Emb * Emb);

    dim3 gg(Emb / 64, Mrows / 64);   // (12, 128)
    gemm_mma_kernel<<<gg, 128>>>(xh, xl, wh + 0 * (size_t)Emb * Emb, wl + 0 * (size_t)Emb * Emb,
                                 bq, 1, nullptr, qh, ql);
    gemm_mma_kernel<<<gg, 128>>>(xh, xl, wh + 1 * (size_t)Emb * Emb, wl + 1 * (size_t)Emb * Emb,
                                 bk, 1, nullptr, kh, kl);
    gemm_mma_kernel<<<gg, 128>>>(xh, xl, wh + 2 * (size_t)Emb * Emb, wl + 2 * (size_t)Emb * Emb,
                                 bv, 2, nullptr, vh, vl);

    dim3 ag(Nseq / 64, NBH);          // (64, 16)
    attn_mma_kernel<<<ag, 128, ATTN_SMEM>>>(qh, ql, kh, kl, vh, vl, ah, al);

    gemm_mma_kernel<<<gg, 128>>>(ah, al, wh + 3 * (size_t)Emb * Emb, wl + 3 * (size_t)Emb * Emb,
                                 bo, 0, out, nullptr, nullptr);
}

// round 3
// speedup vs baseline: 4.0485x; 1.2781x over previous
#include <cuda_runtime.h>
#include <cuda_bf16.h>
#include <stdint.h>
#include <math.h>

#define Mrows   8192
#define Emb     768
#define Nseq    4096
#define Hh      8
#define Dh      96
#define NBH     16

// ---------------- device scratch -------------------------------------------
__device__ __align__(16) __nv_bfloat16 g_xh[Mrows * Emb];
__device__ __align__(16) __nv_bfloat16 g_xl[Mrows * Emb];
__device__ __align__(16) __nv_bfloat16 g_wh[4][Emb * Emb];   // W^T hi [n][k]
__device__ __align__(16) __nv_bfloat16 g_wl[4][Emb * Emb];
__device__ __align__(16) __nv_bfloat16 g_qh[NBH * Nseq * Dh];
__device__ __align__(16) __nv_bfloat16 g_ql[NBH * Nseq * Dh];
__device__ __align__(16) __nv_bfloat16 g_kh[NBH * Nseq * Dh];
__device__ __align__(16) __nv_bfloat16 g_kl[NBH * Nseq * Dh];
__device__ __align__(16) __nv_bfloat16 g_vh[NBH * Dh * Nseq]; // [bh][d][n]
__device__ __align__(16) __nv_bfloat16 g_vl[NBH * Dh * Nseq];
__device__ __align__(16) __nv_bfloat16 g_ah[Mrows * Emb];
__device__ __align__(16) __nv_bfloat16 g_al[Mrows * Emb];

// ---------------- helpers ---------------------------------------------------
__device__ __forceinline__ void mma_bf16(float* c, const uint32_t* a,
                                         uint32_t b0, uint32_t b1)
{
    asm volatile(
        "mma.sync.aligned.m16n8k16.row.col.f32.bf16.bf16.f32 "
        "{%0,%1,%2,%3}, {%4,%5,%6,%7}, {%8,%9}, {%0,%1,%2,%3};\n"
        : "+f"(c[0]), "+f"(c[1]), "+f"(c[2]), "+f"(c[3])
        : "r"(a[0]), "r"(a[1]), "r"(a[2]), "r"(a[3]), "r"(b0), "r"(b1));
}

__device__ __forceinline__ uint32_t pk(float lo, float hi)
{
    uint32_t r;
    asm("cvt.rn.bf16x2.f32 %0, %1, %2;" : "=r"(r) : "f"(hi), "f"(lo));
    return r;
}
__device__ __forceinline__ float rb(float x)
{
    return __bfloat162float(__float2bfloat16(x));
}
__device__ __forceinline__ void splitstore(__nv_bfloat16* H, __nv_bfloat16* L,
                                           size_t idx, float v)
{
    __nv_bfloat16 h = __float2bfloat16(v);
    H[idx] = h;
    L[idx] = __float2bfloat16(v - __bfloat162float(h));
}
__device__ __forceinline__ void cpa16(void* dst, const void* src)
{
    uint32_t d = (uint32_t)__cvta_generic_to_shared(dst);
    asm volatile("cp.async.cg.shared.global [%0], [%1], 16;\n" :: "r"(d), "l"(src));
}
#define CPA_COMMIT asm volatile("cp.async.commit_group;\n" ::: "memory")
#define CPA_WAIT0  asm volatile("cp.async.wait_group 0;\n" ::: "memory")

// ---------------- conversion kernels ---------------------------------------
// x: vectorized float4 -> bf16 hi/lo
__global__ void conv_split_kernel(const float4* __restrict__ X,
                                  uint2* __restrict__ H, uint2* __restrict__ L,
                                  int n4)
{
    int i = blockIdx.x * 256 + threadIdx.x;
    if (i < n4) {
        float4 v = X[i];
        float h0 = rb(v.x), h1 = rb(v.y), h2 = rb(v.z), h3 = rb(v.w);
        uint2 hh, ll;
        hh.x = pk(h0, h1); hh.y = pk(h2, h3);
        ll.x = pk(v.x - h0, v.y - h1);
        ll.y = pk(v.z - h2, v.w - h3);
        H[i] = hh;
        L[i] = ll;
    }
}

// W [k][n] fp32 -> W^T hi/lo [n][k] via smem transpose; z selects weight
__global__ void conv_w_kernel(const float* __restrict__ W0,
                              const float* __restrict__ W1,
                              const float* __restrict__ W2,
                              const float* __restrict__ W3,
                              __nv_bfloat16* __restrict__ H,
                              __nv_bfloat16* __restrict__ L)
{
    __shared__ float t[32][33];
    int z = blockIdx.z;
    const float* W = (z == 0) ? W0 : (z == 1) ? W1 : (z == 2) ? W2 : W3;
    __nv_bfloat16* Hd = H + (size_t)z * Emb * Emb;
    __nv_bfloat16* Ld = L + (size_t)z * Emb * Emb;

    int n0 = blockIdx.x * 32, k0 = blockIdx.y * 32;
    int tx = threadIdx.x, ty = threadIdx.y;  // 32 x 8
#pragma unroll
    for (int i = 0; i < 4; i++)
        t[ty + 8 * i][tx] = W[(size_t)(k0 + ty + 8 * i) * Emb + n0 + tx];
    __syncthreads();
#pragma unroll
    for (int i = 0; i < 4; i++) {
        int n = n0 + ty + 8 * i, k = k0 + tx;
        float v = t[tx][ty + 8 * i];
        __nv_bfloat16 h = __float2bfloat16(v);
        Hd[(size_t)n * Emb + k] = h;
        Ld[(size_t)n * Emb + k] = __float2bfloat16(v - __bfloat162float(h));
    }
}

// ---------------- split-bf16 GEMM: 128x64 tile, 2-stage cp.async ------------
#define GSTR 24
__global__ __launch_bounds__(256) void gemm_mma_kernel(
    const __nv_bfloat16* __restrict__ Ah, const __nv_bfloat16* __restrict__ Al,
    const __nv_bfloat16* __restrict__ Bh, const __nv_bfloat16* __restrict__ Bl,
    const float* __restrict__ bias, int mode,
    float* __restrict__ Cf,
    __nv_bfloat16* __restrict__ Ch, __nv_bfloat16* __restrict__ Cl)
{
    __shared__ __nv_bfloat16 sA[2][2][128 * GSTR];  // [stage][hi/lo]
    __shared__ __nv_bfloat16 sB[2][2][64 * GSTR];

    const int tid = threadIdx.x;
    const int warp = tid >> 5, lane = tid & 31;
    const int g = lane >> 2, t = lane & 3;
    const int wm = warp >> 1, wn = warp & 1;
    const int row0 = blockIdx.y * 128, col0 = blockIdx.x * 64;

    float acc[2][4][4];
#pragma unroll
    for (int i = 0; i < 2; i++)
#pragma unroll
        for (int j = 0; j < 4; j++)
#pragma unroll
            for (int c = 0; c < 4; c++) acc[i][j][c] = 0.f;

    // stage issue: 256 thr: A hi/lo (128 rows x 2 chunks), B hi/lo (64 x 2)
    auto issue = [&](int k0, int st) {
        int r = tid >> 1, c = tid & 1;
        cpa16(&sA[st][0][r * GSTR + c * 8],
              Ah + (size_t)(row0 + r) * Emb + k0 + c * 8);
        cpa16(&sA[st][1][r * GSTR + c * 8],
              Al + (size_t)(row0 + r) * Emb + k0 + c * 8);
        if (tid < 128) {
            cpa16(&sB[st][0][r * GSTR + c * 8],
                  Bh + (size_t)(col0 + r) * Emb + k0 + c * 8);
        } else {
            int r2 = (tid - 128) >> 1;
            cpa16(&sB[st][1][r2 * GSTR + c * 8],
                  Bl + (size_t)(col0 + r2) * Emb + k0 + c * 8);
        }
    };

    issue(0, 0);
    CPA_COMMIT;

    for (int kk = 0; kk < 48; kk++) {
        int cur = kk & 1;
        CPA_WAIT0;
        __syncthreads();
        if (kk + 1 < 48) { issue((kk + 1) * 16, 1 - cur); CPA_COMMIT; }

        uint32_t ah[2][4], al2[2][4];
#pragma unroll
        for (int mb = 0; mb < 2; mb++) {
            int rr = wm * 32 + mb * 16 + g;
            int cc = 2 * t;
            ah[mb][0] = *(const uint32_t*)&sA[cur][0][rr * GSTR + cc];
            ah[mb][1] = *(const uint32_t*)&sA[cur][0][(rr + 8) * GSTR + cc];
            ah[mb][2] = *(const uint32_t*)&sA[cur][0][rr * GSTR + cc + 8];
            ah[mb][3] = *(const uint32_t*)&sA[cur][0][(rr + 8) * GSTR + cc + 8];
            al2[mb][0] = *(const uint32_t*)&sA[cur][1][rr * GSTR + cc];
            al2[mb][1] = *(const uint32_t*)&sA[cur][1][(rr + 8) * GSTR + cc];
            al2[mb][2] = *(const uint32_t*)&sA[cur][1][rr * GSTR + cc + 8];
            al2[mb][3] = *(const uint32_t*)&sA[cur][1][(rr + 8) * GSTR + cc + 8];
        }
#pragma unroll
        for (int nb = 0; nb < 4; nb++) {
            int cn = wn * 32 + nb * 8 + g;
            uint32_t bh0 = *(const uint32_t*)&sB[cur][0][cn * GSTR + 2 * t];
            uint32_t bh1 = *(const uint32_t*)&sB[cur][0][cn * GSTR + 8 + 2 * t];
            uint32_t bl0 = *(const uint32_t*)&sB[cur][1][cn * GSTR + 2 * t];
            uint32_t bl1 = *(const uint32_t*)&sB[cur][1][cn * GSTR + 8 + 2 * t];
#pragma unroll
            for (int mb = 0; mb < 2; mb++) {
                mma_bf16(acc[mb][nb], ah[mb], bh0, bh1);
                mma_bf16(acc[mb][nb], ah[mb], bl0, bl1);
                mma_bf16(acc[mb][nb], al2[mb], bh0, bh1);
            }
        }
        __syncthreads();
    }

#pragma unroll
    for (int mb = 0; mb < 2; mb++) {
#pragma unroll
        for (int nb = 0; nb < 4; nb++) {
            int r = row0 + wm * 32 + mb * 16 + g;
            int cb = col0 + wn * 32 + nb * 8 + 2 * t;
#pragma unroll
            for (int c = 0; c < 4; c++) {
                int rr = r + (c >= 2 ? 8 : 0);
                int cc = cb + (c & 1);
                float v = acc[mb][nb][c] + bias[cc];
                if (mode == 0) {
                    Cf[(size_t)rr * Emb + cc] = v;
                } else {
                    int b = rr >> 12, n = rr & 4095;
                    int h = cc / Dh, d = cc - h * Dh;
                    size_t idx;
                    if (mode == 1)
                        idx = ((size_t)(b * Hh + h) * Nseq + n) * Dh + d;
                    else
                        idx = ((size_t)(b * Hh + h) * Dh + d) * Nseq + n;
                    splitstore(Ch, Cl, idx, v);
                }
            }
        }
    }
}

// ---------------- flash attention: 128q x 64k, 8 warps, 2-stage cp.async ----
#define QS 120
#define VS 88
#define OFF_QH 0
#define OFF_QL 30720
#define STAGE0 61440
#define STAGE_SZ 64512
#define S_KH 0
#define S_KL 15360
#define S_VH 30720
#define S_VL 47616
#define ATTN_SMEM (STAGE0 + 2 * STAGE_SZ)   // 190464

__global__ __launch_bounds__(256) void attn_mma_kernel(
    const __nv_bfloat16* __restrict__ Qh, const __nv_bfloat16* __restrict__ Ql,
    const __nv_bfloat16* __restrict__ Kh, const __nv_bfloat16* __restrict__ Kl,
    const __nv_bfloat16* __restrict__ Vh, const __nv_bfloat16* __restrict__ Vl,
    __nv_bfloat16* __restrict__ Oh, __nv_bfloat16* __restrict__ Ol)
{
    extern __shared__ char sm[];
    const int tid = threadIdx.x;
    const int warp = tid >> 5, lane = tid & 31;
    const int g = lane >> 2, t = lane & 3;
    const int bh = blockIdx.y;
    const int q0 = blockIdx.x * 128;

    // --- async load Q (128 x 96, hi/lo)
    {
        const char* gQh = (const char*)(Qh + ((size_t)bh * Nseq + q0) * Dh);
        const char* gQl = (const char*)(Ql + ((size_t)bh * Nseq + q0) * Dh);
#pragma unroll
        for (int j = 0; j < 6; j++) {
            int idx = tid + j * 256;          // 1536 chunks
            int r = idx / 12, c = idx - r * 12;
            cpa16(sm + OFF_QH + r * 240 + c * 16, gQh + (size_t)r * 192 + c * 16);
            cpa16(sm + OFF_QL + r * 240 + c * 16, gQl + (size_t)r * 192 + c * 16);
        }
    }

    // --- stage issue for K/V tile kt
    auto issue = [&](int kt, int st) {
        char* base = sm + STAGE0 + st * STAGE_SZ;
        const char* gKh = (const char*)(Kh + ((size_t)bh * Nseq + kt * 64) * Dh);
        const char* gKl = (const char*)(Kl + ((size_t)bh * Nseq + kt * 64) * Dh);
        const char* gVh = (const char*)(Vh + (size_t)bh * Dh * Nseq + kt * 64);
        const char* gVl = (const char*)(Vl + (size_t)bh * Dh * Nseq + kt * 64);
#pragma unroll
        for (int j = 0; j < 3; j++) {
            int idx = tid + j * 256;          // 768 chunks each
            int r = idx / 12, c = idx - r * 12;
            cpa16(base + S_KH + r * 240 + c * 16, gKh + (size_t)r * 192 + c * 16);
            cpa16(base + S_KL + r * 240 + c * 16, gKl + (size_t)r * 192 + c * 16);
            int rv = idx >> 3, cv = idx & 7;
            cpa16(base + S_VH + rv * 176 + cv * 16, gVh + (size_t)rv * 8192 + cv * 16);
            cpa16(base + S_VL + rv * 176 + cv * 16, gVl + (size_t)rv * 8192 + cv * 16);
        }
    };

    issue(0, 0);
    CPA_COMMIT;
    CPA_WAIT0;
    __syncthreads();

    // --- Q fragments (register resident)
    uint32_t qh[6][4], ql[6][4];
    {
        const __nv_bfloat16* sQh = (const __nv_bfloat16*)(sm + OFF_QH);
        const __nv_bfloat16* sQl = (const __nv_bfloat16*)(sm + OFF_QL);
        int r0 = warp * 16 + g;
#pragma unroll
        for (int kb = 0; kb < 6; kb++) {
            int c0 = kb * 16 + 2 * t;
            qh[kb][0] = *(const uint32_t*)(sQh + r0 * QS + c0);
            qh[kb][1] = *(const uint32_t*)(sQh + (r0 + 8) * QS + c0);
            qh[kb][2] = *(const uint32_t*)(sQh + r0 * QS + c0 + 8);
            qh[kb][3] = *(const uint32_t*)(sQh + (r0 + 8) * QS + c0 + 8);
            ql[kb][0] = *(const uint32_t*)(sQl + r0 * QS + c0);
            ql[kb][1] = *(const uint32_t*)(sQl + (r0 + 8) * QS + c0);
            ql[kb][2] = *(const uint32_t*)(sQl + r0 * QS + c0 + 8);
            ql[kb][3] = *(const uint32_t*)(sQl + (r0 + 8) * QS + c0 + 8);
        }
    }

    float o[12][4];
#pragma unroll
    for (int i = 0; i < 12; i++)
#pragma unroll
        for (int c = 0; c < 4; c++) o[i][c] = 0.f;
    float m0 = -1e30f, m1 = -1e30f, l0 = 0.f, l1 = 0.f;

    for (int kt = 0; kt < 64; kt++) {
        int cur = kt & 1;
        if (kt > 0) { CPA_WAIT0; }
        __syncthreads();
        if (kt + 1 < 64) { issue(kt + 1, 1 - cur); CPA_COMMIT; }

        const char* base = sm + STAGE0 + cur * STAGE_SZ;
        const __nv_bfloat16* sKh = (const __nv_bfloat16*)(base + S_KH);
        const __nv_bfloat16* sKl = (const __nv_bfloat16*)(base + S_KL);
        const __nv_bfloat16* sVh = (const __nv_bfloat16*)(base + S_VH);
        const __nv_bfloat16* sVl = (const __nv_bfloat16*)(base + S_VL);

        // --- S = Q K^T
        float s[8][4];
#pragma unroll
        for (int nb = 0; nb < 8; nb++)
#pragma unroll
            for (int c = 0; c < 4; c++) s[nb][c] = 0.f;

#pragma unroll
        for (int kb = 0; kb < 6; kb++) {
#pragma unroll
            for (int nb = 0; nb < 8; nb++) {
                const __nv_bfloat16* kr = sKh + (nb * 8 + g) * QS + kb * 16 + 2 * t;
                const __nv_bfloat16* krl = sKl + (nb * 8 + g) * QS + kb * 16 + 2 * t;
                uint32_t bh0 = *(const uint32_t*)kr;
                uint32_t bh1 = *(const uint32_t*)(kr + 8);
                uint32_t bl0 = *(const uint32_t*)krl;
                uint32_t bl1 = *(const uint32_t*)(krl + 8);
                mma_bf16(s[nb], qh[kb], bh0, bh1);
                mma_bf16(s[nb], qh[kb], bl0, bl1);
                mma_bf16(s[nb], ql[kb], bh0, bh1);
            }
        }

        // --- online softmax
        float mx0 = -1e30f, mx1 = -1e30f;
#pragma unroll
        for (int nb = 0; nb < 8; nb++) {
            mx0 = fmaxf(mx0, fmaxf(s[nb][0], s[nb][1]));
            mx1 = fmaxf(mx1, fmaxf(s[nb][2], s[nb][3]));
        }
        mx0 = fmaxf(mx0, __shfl_xor_sync(0xffffffffu, mx0, 1));
        mx0 = fmaxf(mx0, __shfl_xor_sync(0xffffffffu, mx0, 2));
        mx1 = fmaxf(mx1, __shfl_xor_sync(0xffffffffu, mx1, 1));
        mx1 = fmaxf(mx1, __shfl_xor_sync(0xffffffffu, mx1, 2));

        float nm0 = fmaxf(m0, mx0), nm1 = fmaxf(m1, mx1);
        float sc0 = __expf(m0 - nm0), sc1 = __expf(m1 - nm1);
        float rs0 = 0.f, rs1 = 0.f;
#pragma unroll
        for (int nb = 0; nb < 8; nb++) {
            s[nb][0] = __expf(s[nb][0] - nm0);
            s[nb][1] = __expf(s[nb][1] - nm0);
            s[nb][2] = __expf(s[nb][2] - nm1);
            s[nb][3] = __expf(s[nb][3] - nm1);
            rs0 += s[nb][0] + s[nb][1];
            rs1 += s[nb][2] + s[nb][3];
        }
        rs0 += __shfl_xor_sync(0xffffffffu, rs0, 1);
        rs0 += __shfl_xor_sync(0xffffffffu, rs0, 2);
        rs1 += __shfl_xor_sync(0xffffffffu, rs1, 1);
        rs1 += __shfl_xor_sync(0xffffffffu, rs1, 2);
        l0 = l0 * sc0 + rs0;
        l1 = l1 * sc1 + rs1;
        m0 = nm0;
        m1 = nm1;
#pragma unroll
        for (int nbd = 0; nbd < 12; nbd++) {
            o[nbd][0] *= sc0;
            o[nbd][1] *= sc0;
            o[nbd][2] *= sc1;
            o[nbd][3] *= sc1;
        }

        // --- O += P V
#pragma unroll
        for (int kb = 0; kb < 4; kb++) {
            float a0 = s[2 * kb][0], a1 = s[2 * kb][1];
            float a2 = s[2 * kb][2], a3 = s[2 * kb][3];
            float b0 = s[2 * kb + 1][0], b1 = s[2 * kb + 1][1];
            float b2 = s[2 * kb + 1][2], b3 = s[2 * kb + 1][3];
            uint32_t PH[4], PL[4];
            PH[0] = pk(a0, a1); PH[1] = pk(a2, a3);
            PH[2] = pk(b0, b1); PH[3] = pk(b2, b3);
            PL[0] = pk(a0 - rb(a0), a1 - rb(a1));
            PL[1] = pk(a2 - rb(a2), a3 - rb(a3));
            PL[2] = pk(b0 - rb(b0), b1 - rb(b1));
            PL[3] = pk(b2 - rb(b2), b3 - rb(b3));
#pragma unroll
            for (int nbd = 0; nbd < 12; nbd++) {
                const __nv_bfloat16* vr = sVh + (nbd * 8 + g) * VS + kb * 16 + 2 * t;
                const __nv_bfloat16* vrl = sVl + (nbd * 8 + g) * VS + kb * 16 + 2 * t;
                uint32_t vh0 = *(const uint32_t*)vr;
                uint32_t vh1 = *(const uint32_t*)(vr + 8);
                uint32_t vl0 = *(const uint32_t*)vrl;
                uint32_t vl1 = *(const uint32_t*)(vrl + 8);
                mma_bf16(o[nbd], PH, vh0, vh1);
                mma_bf16(o[nbd], PH, vl0, vl1);
                mma_bf16(o[nbd], PL, vh0, vh1);
            }
        }
    }

    // --- epilogue
    const float isq = 0.1020620726159657f;   // 1/sqrt(96)
    float iv0 = isq / l0, iv1 = isq / l1;
    int b = bh >> 3, h = bh & 7;
    int r0 = q0 + warp * 16 + g;
    size_t row0 = (size_t)b * Nseq + r0;
    size_t row1 = row0 + 8;
#pragma unroll
    for (int nbd = 0; nbd < 12; nbd++) {
        int e = h * Dh + nbd * 8 + 2 * t;
        splitstore(Oh, Ol, row0 * Emb + e, o[nbd][0] * iv0);
        splitstore(Oh, Ol, row0 * Emb + e + 1, o[nbd][1] * iv0);
        splitstore(Oh, Ol, row1 * Emb + e, o[nbd][2] * iv1);
        splitstore(Oh, Ol, row1 * Emb + e + 1, o[nbd][3] * iv1);
    }
}

// ---------------------------------------------------------------------------
extern "C" void kernel_launch(void* const* d_in, const int* in_sizes, int n_in,
                              void* d_out, int out_size)
{
    const float* x  = (const float*)d_in[0];
    const float* Wq = (const float*)d_in[1];
    const float* bq = (const float*)d_in[2];
    const float* Wk = (const float*)d_in[3];
    const float* bk = (const float*)d_in[4];
    const float* Wv = (const float*)d_in[5];
    const float* bv = (const float*)d_in[6];
    const float* Wo = (const float*)d_in[7];
    const float* bo = (const float*)d_in[8];
    float* out = (float*)d_out;

    __nv_bfloat16 *xh, *xl, *wh, *wl, *qh, *ql, *kh, *kl, *vh, *vl, *ah, *al;
    cudaGetSymbolAddress((void**)&xh, g_xh);
    cudaGetSymbolAddress((void**)&xl, g_xl);
    cudaGetSymbolAddress((void**)&wh, g_wh);
    cudaGetSymbolAddress((void**)&wl, g_wl);
    cudaGetSymbolAddress((void**)&qh, g_qh);
    cudaGetSymbolAddress((void**)&ql, g_ql);
    cudaGetSymbolAddress((void**)&kh, g_kh);
    cudaGetSymbolAddress((void**)&kl, g_kl);
    cudaGetSymbolAddress((void**)&vh, g_vh);
    cudaGetSymbolAddress((void**)&vl, g_vl);
    cudaGetSymbolAddress((void**)&ah, g_ah);
    cudaGetSymbolAddress((void**)&al, g_al);

    cudaFuncSetAttribute(attn_mma_kernel,
                         cudaFuncAttributeMaxDynamicSharedMemorySize, ATTN_SMEM);

    // conversions
    conv_split_kernel<<<(Mrows * Emb / 4 + 255) / 256, 256>>>(
        (const float4*)x, (uint2*)xh, (uint2*)xl, Mrows * Emb / 4);
    dim3 wg(Emb / 32, Emb / 32, 4);
    conv_w_kernel<<<wg, dim3(32, 8)>>>(Wq, Wk, Wv, Wo, wh, wl);

    dim3 gg(Emb / 64, Mrows / 128);   // (12, 64)
    gemm_mma_kernel<<<gg, 256>>>(xh, xl, wh + 0 * (size_t)Emb * Emb, wl + 0 * (size_t)Emb * Emb,
                                 bq, 1, nullptr, qh, ql);
    gemm_mma_kernel<<<gg, 256>>>(xh, xl, wh + 1 * (size_t)Emb * Emb, wl + 1 * (size_t)Emb * Emb,
                                 bk, 1, nullptr, kh, kl);
    gemm_mma_kernel<<<gg, 256>>>(xh, xl, wh + 2 * (size_t)Emb * Emb, wl + 2 * (size_t)Emb * Emb,
                                 bv, 2, nullptr, vh, vl);

    dim3 ag(Nseq / 128, NBH);         // (32, 16)
    attn_mma_kernel<<<ag, 256, ATTN_SMEM>>>(qh, ql, kh, kl, vh, vl, ah, al);

    gemm_mma_kernel<<<gg, 256>>>(ah, al, wh + 3 * (size_t)Emb * Emb, wl + 3 * (size_t)Emb * Emb,
                                 bo, 0, out, nullptr, nullptr);
}

// round 4
// speedup vs baseline: 4.3120x; 1.0651x over previous
#include <cuda_runtime.h>
#include <cuda_bf16.h>
#include <stdint.h>
#include <math.h>

#define Mrows   8192
#define Emb     768
#define Nseq    4096
#define Hh      8
#define Dh      96
#define NBH     16

// ---------------- device scratch -------------------------------------------
__device__ __align__(16) __nv_bfloat16 g_xh[Mrows * Emb];
__device__ __align__(16) __nv_bfloat16 g_xl[Mrows * Emb];
__device__ __align__(16) __nv_bfloat16 g_wh[4][Emb * Emb];   // W^T hi [n][k]
__device__ __align__(16) __nv_bfloat16 g_wl[4][Emb * Emb];
__device__ __align__(16) __nv_bfloat16 g_qh[NBH * Nseq * Dh];
__device__ __align__(16) __nv_bfloat16 g_ql[NBH * Nseq * Dh];
__device__ __align__(16) __nv_bfloat16 g_kh[NBH * Nseq * Dh];
__device__ __align__(16) __nv_bfloat16 g_kl[NBH * Nseq * Dh];
__device__ __align__(16) __nv_bfloat16 g_vh[NBH * Dh * Nseq]; // [bh][d][n]
__device__ __align__(16) __nv_bfloat16 g_vl[NBH * Dh * Nseq];
__device__ __align__(16) __nv_bfloat16 g_ah[Mrows * Emb];
__device__ __align__(16) __nv_bfloat16 g_al[Mrows * Emb];

// ---------------- helpers ---------------------------------------------------
__device__ __forceinline__ void mma_bf16(float* c, const uint32_t* a,
                                         uint32_t b0, uint32_t b1)
{
    asm volatile(
        "mma.sync.aligned.m16n8k16.row.col.f32.bf16.bf16.f32 "
        "{%0,%1,%2,%3}, {%4,%5,%6,%7}, {%8,%9}, {%0,%1,%2,%3};\n"
        : "+f"(c[0]), "+f"(c[1]), "+f"(c[2]), "+f"(c[3])
        : "r"(a[0]), "r"(a[1]), "r"(a[2]), "r"(a[3]), "r"(b0), "r"(b1));
}

__device__ __forceinline__ void ldsm4(uint32_t* r, const void* p)
{
    uint32_t a = (uint32_t)__cvta_generic_to_shared(p);
    asm volatile("ldmatrix.sync.aligned.m8n8.x4.shared.b16 {%0,%1,%2,%3}, [%4];\n"
                 : "=r"(r[0]), "=r"(r[1]), "=r"(r[2]), "=r"(r[3]) : "r"(a));
}

__device__ __forceinline__ uint32_t pk(float lo, float hi)
{
    uint32_t r;
    asm("cvt.rn.bf16x2.f32 %0, %1, %2;" : "=r"(r) : "f"(hi), "f"(lo));
    return r;
}
__device__ __forceinline__ float rb(float x)
{
    return __bfloat162float(__float2bfloat16(x));
}
__device__ __forceinline__ void splitstore(__nv_bfloat16* H, __nv_bfloat16* L,
                                           size_t idx, float v)
{
    __nv_bfloat16 h = __float2bfloat16(v);
    H[idx] = h;
    L[idx] = __float2bfloat16(v - __bfloat162float(h));
}
__device__ __forceinline__ void cpa16(void* dst, const void* src)
{
    uint32_t d = (uint32_t)__cvta_generic_to_shared(dst);
    asm volatile("cp.async.cg.shared.global [%0], [%1], 16;\n" :: "r"(d), "l"(src));
}
#define CPA_COMMIT asm volatile("cp.async.commit_group;\n" ::: "memory")
#define CPA_WAIT0  asm volatile("cp.async.wait_group 0;\n" ::: "memory")
#define CPA_WAIT2  asm volatile("cp.async.wait_group 2;\n" ::: "memory")

// ---------------- conversion kernels ---------------------------------------
__global__ void conv_split_kernel(const float4* __restrict__ X,
                                  uint2* __restrict__ H, uint2* __restrict__ L,
                                  int n4)
{
    int i = blockIdx.x * 256 + threadIdx.x;
    if (i < n4) {
        float4 v = X[i];
        float h0 = rb(v.x), h1 = rb(v.y), h2 = rb(v.z), h3 = rb(v.w);
        uint2 hh, ll;
        hh.x = pk(h0, h1); hh.y = pk(h2, h3);
        ll.x = pk(v.x - h0, v.y - h1);
        ll.y = pk(v.z - h2, v.w - h3);
        H[i] = hh;
        L[i] = ll;
    }
}

__global__ void conv_w_kernel(const float* __restrict__ W0,
                              const float* __restrict__ W1,
                              const float* __restrict__ W2,
                              const float* __restrict__ W3,
                              __nv_bfloat16* __restrict__ H,
                              __nv_bfloat16* __restrict__ L)
{
    __shared__ float t[32][33];
    int z = blockIdx.z;
    const float* W = (z == 0) ? W0 : (z == 1) ? W1 : (z == 2) ? W2 : W3;
    __nv_bfloat16* Hd = H + (size_t)z * Emb * Emb;
    __nv_bfloat16* Ld = L + (size_t)z * Emb * Emb;

    int n0 = blockIdx.x * 32, k0 = blockIdx.y * 32;
    int tx = threadIdx.x, ty = threadIdx.y;
#pragma unroll
    for (int i = 0; i < 4; i++)
        t[ty + 8 * i][tx] = W[(size_t)(k0 + ty + 8 * i) * Emb + n0 + tx];
    __syncthreads();
#pragma unroll
    for (int i = 0; i < 4; i++) {
        int n = n0 + ty + 8 * i, k = k0 + tx;
        float v = t[tx][ty + 8 * i];
        __nv_bfloat16 h = __float2bfloat16(v);
        Hd[(size_t)n * Emb + k] = h;
        Ld[(size_t)n * Emb + k] = __float2bfloat16(v - __bfloat162float(h));
    }
}

// ---------------- split-bf16 GEMM: 128x64 tile, 4-stage cp.async ------------
#define GSTR 24
#define G_STG 18432
#define G_AH  0
#define G_AL  6144
#define G_BH  12288
#define G_BL  15360
#define GEMM_SMEM (4 * G_STG)   // 73728

__global__ __launch_bounds__(256) void gemm_mma_kernel(
    const __nv_bfloat16* __restrict__ Ah, const __nv_bfloat16* __restrict__ Al,
    const __nv_bfloat16* __restrict__ Bh, const __nv_bfloat16* __restrict__ Bl,
    const float* __restrict__ bias, int mode,
    float* __restrict__ Cf,
    __nv_bfloat16* __restrict__ Ch, __nv_bfloat16* __restrict__ Cl)
{
    extern __shared__ char gsm[];
    const int tid = threadIdx.x;
    const int warp = tid >> 5, lane = tid & 31;
    const int g = lane >> 2, t = lane & 3;
    const int lrow = lane & 7, lsel = lane >> 3;
    const int wm = warp >> 1, wn = warp & 1;
    const int row0 = blockIdx.y * 128, col0 = blockIdx.x * 64;

    float acc[2][4][4];
#pragma unroll
    for (int i = 0; i < 2; i++)
#pragma unroll
        for (int j = 0; j < 4; j++)
#pragma unroll
            for (int c = 0; c < 4; c++) acc[i][j][c] = 0.f;

    auto issue = [&](int k0, int st) {
        char* base = gsm + st * G_STG;
        int r = tid >> 1, c = tid & 1;
        cpa16(base + G_AH + (r * GSTR + c * 8) * 2,
              Ah + (size_t)(row0 + r) * Emb + k0 + c * 8);
        cpa16(base + G_AL + (r * GSTR + c * 8) * 2,
              Al + (size_t)(row0 + r) * Emb + k0 + c * 8);
        if (tid < 128) {
            cpa16(base + G_BH + (r * GSTR + c * 8) * 2,
                  Bh + (size_t)(col0 + r) * Emb + k0 + c * 8);
        } else {
            int r2 = (tid - 128) >> 1;
            cpa16(base + G_BL + (r2 * GSTR + c * 8) * 2,
                  Bl + (size_t)(col0 + r2) * Emb + k0 + c * 8);
        }
    };

    issue(0, 0);  CPA_COMMIT;
    issue(16, 1); CPA_COMMIT;
    issue(32, 2); CPA_COMMIT;

    // A frag address offsets (elements): row-pairs first, then k-halves
    const int aRow = (lsel & 1) ? 8 : 0;
    const int aCol = (lsel >> 1) ? 8 : 0;
    // B frag: k-halves first, then row-pairs (r0,r1 = nb even; r2,r3 = nb odd)
    const int bRow = (lsel >> 1) ? 8 : 0;
    const int bCol = (lsel & 1) ? 8 : 0;

    for (int kk = 0; kk < 48; kk++) {
        CPA_WAIT2;
        __syncthreads();
        if (kk + 3 < 48) issue((kk + 3) * 16, (kk + 3) & 3);
        CPA_COMMIT;

        char* base = gsm + (kk & 3) * G_STG;
        const __nv_bfloat16* pAh = (const __nv_bfloat16*)(base + G_AH);
        const __nv_bfloat16* pAl = (const __nv_bfloat16*)(base + G_AL);
        const __nv_bfloat16* pBh = (const __nv_bfloat16*)(base + G_BH);
        const __nv_bfloat16* pBl = (const __nv_bfloat16*)(base + G_BL);

        uint32_t ah[2][4], al2[2][4];
#pragma unroll
        for (int mb = 0; mb < 2; mb++) {
            int rr = wm * 32 + mb * 16 + aRow + lrow;
            ldsm4(ah[mb], pAh + rr * GSTR + aCol);
            ldsm4(al2[mb], pAl + rr * GSTR + aCol);
        }
#pragma unroll
        for (int p = 0; p < 2; p++) {
            int cn = wn * 32 + p * 16 + bRow + lrow;
            uint32_t bhv[4], blv[4];
            ldsm4(bhv, pBh + cn * GSTR + bCol);
            ldsm4(blv, pBl + cn * GSTR + bCol);
#pragma unroll
            for (int mb = 0; mb < 2; mb++) {
                mma_bf16(acc[mb][2 * p], ah[mb], bhv[0], bhv[1]);
                mma_bf16(acc[mb][2 * p], ah[mb], blv[0], blv[1]);
                mma_bf16(acc[mb][2 * p], al2[mb], bhv[0], bhv[1]);
                mma_bf16(acc[mb][2 * p + 1], ah[mb], bhv[2], bhv[3]);
                mma_bf16(acc[mb][2 * p + 1], ah[mb], blv[2], blv[3]);
                mma_bf16(acc[mb][2 * p + 1], al2[mb], bhv[2], bhv[3]);
            }
        }
    }

#pragma unroll
    for (int mb = 0; mb < 2; mb++) {
#pragma unroll
        for (int nb = 0; nb < 4; nb++) {
            int r = row0 + wm * 32 + mb * 16 + g;
            int cb = col0 + wn * 32 + nb * 8 + 2 * t;
#pragma unroll
            for (int c = 0; c < 4; c++) {
                int rr = r + (c >= 2 ? 8 : 0);
                int cc = cb + (c & 1);
                float v = acc[mb][nb][c] + bias[cc];
                if (mode == 0) {
                    Cf[(size_t)rr * Emb + cc] = v;
                } else {
                    int b = rr >> 12, n = rr & 4095;
                    int h = cc / Dh, d = cc - h * Dh;
                    size_t idx;
                    if (mode == 1)
                        idx = ((size_t)(b * Hh + h) * Nseq + n) * Dh + d;
                    else
                        idx = ((size_t)(b * Hh + h) * Dh + d) * Nseq + n;
                    splitstore(Ch, Cl, idx, v);
                }
            }
        }
    }
}

// ---------------- flash attention: 128q x 64k, 8 warps, ldmatrix ------------
#define QS 120
#define VS 88
#define OFF_QH 0
#define OFF_QL 30720
#define STAGE0 61440
#define STAGE_SZ 64512
#define S_KH 0
#define S_KL 15360
#define S_VH 30720
#define S_VL 47616
#define ATTN_SMEM (STAGE0 + 2 * STAGE_SZ)   // 190464

__global__ __launch_bounds__(256) void attn_mma_kernel(
    const __nv_bfloat16* __restrict__ Qh, const __nv_bfloat16* __restrict__ Ql,
    const __nv_bfloat16* __restrict__ Kh, const __nv_bfloat16* __restrict__ Kl,
    const __nv_bfloat16* __restrict__ Vh, const __nv_bfloat16* __restrict__ Vl,
    __nv_bfloat16* __restrict__ Oh, __nv_bfloat16* __restrict__ Ol)
{
    extern __shared__ char sm[];
    const int tid = threadIdx.x;
    const int warp = tid >> 5, lane = tid & 31;
    const int g = lane >> 2, t = lane & 3;
    const int lrow = lane & 7, lsel = lane >> 3;
    const int bh = blockIdx.y;
    const int q0 = blockIdx.x * 128;

    {
        const char* gQh = (const char*)(Qh + ((size_t)bh * Nseq + q0) * Dh);
        const char* gQl = (const char*)(Ql + ((size_t)bh * Nseq + q0) * Dh);
#pragma unroll
        for (int j = 0; j < 6; j++) {
            int idx = tid + j * 256;
            int r = idx / 12, c = idx - r * 12;
            cpa16(sm + OFF_QH + r * 240 + c * 16, gQh + (size_t)r * 192 + c * 16);
            cpa16(sm + OFF_QL + r * 240 + c * 16, gQl + (size_t)r * 192 + c * 16);
        }
    }

    auto issue = [&](int kt, int st) {
        char* base = sm + STAGE0 + st * STAGE_SZ;
        const char* gKh = (const char*)(Kh + ((size_t)bh * Nseq + kt * 64) * Dh);
        const char* gKl = (const char*)(Kl + ((size_t)bh * Nseq + kt * 64) * Dh);
        const char* gVh = (const char*)(Vh + (size_t)bh * Dh * Nseq + kt * 64);
        const char* gVl = (const char*)(Vl + (size_t)bh * Dh * Nseq + kt * 64);
#pragma unroll
        for (int j = 0; j < 3; j++) {
            int idx = tid + j * 256;
            int r = idx / 12, c = idx - r * 12;
            cpa16(base + S_KH + r * 240 + c * 16, gKh + (size_t)r * 192 + c * 16);
            cpa16(base + S_KL + r * 240 + c * 16, gKl + (size_t)r * 192 + c * 16);
            int rv = idx >> 3, cv = idx & 7;
            cpa16(base + S_VH + rv * 176 + cv * 16, gVh + (size_t)rv * 8192 + cv * 16);
            cpa16(base + S_VL + rv * 176 + cv * 16, gVl + (size_t)rv * 8192 + cv * 16);
        }
    };

    issue(0, 0);
    CPA_COMMIT;
    CPA_WAIT0;
    __syncthreads();

    // Q fragments via ldmatrix (row-pairs then k-halves)
    const int aRow = (lsel & 1) ? 8 : 0;
    const int aCol = (lsel >> 1) ? 8 : 0;
    // B frag: k-halves first then row-pairs
    const int bRow = (lsel >> 1) ? 8 : 0;
    const int bCol = (lsel & 1) ? 8 : 0;

    uint32_t qh[6][4], ql[6][4];
    {
        const __nv_bfloat16* sQh = (const __nv_bfloat16*)(sm + OFF_QH);
        const __nv_bfloat16* sQl = (const __nv_bfloat16*)(sm + OFF_QL);
        int r0 = warp * 16 + aRow + lrow;
#pragma unroll
        for (int kb = 0; kb < 6; kb++) {
            ldsm4(qh[kb], sQh + r0 * QS + kb * 16 + aCol);
            ldsm4(ql[kb], sQl + r0 * QS + kb * 16 + aCol);
        }
    }

    float o[12][4];
#pragma unroll
    for (int i = 0; i < 12; i++)
#pragma unroll
        for (int c = 0; c < 4; c++) o[i][c] = 0.f;
    float m0 = -1e30f, m1 = -1e30f, l0 = 0.f, l1 = 0.f;

    for (int kt = 0; kt < 64; kt++) {
        int cur = kt & 1;
        if (kt > 0) { CPA_WAIT0; }
        __syncthreads();
        if (kt + 1 < 64) { issue(kt + 1, 1 - cur); CPA_COMMIT; }

        const char* base = sm + STAGE0 + cur * STAGE_SZ;
        const __nv_bfloat16* sKh = (const __nv_bfloat16*)(base + S_KH);
        const __nv_bfloat16* sKl = (const __nv_bfloat16*)(base + S_KL);
        const __nv_bfloat16* sVh = (const __nv_bfloat16*)(base + S_VH);
        const __nv_bfloat16* sVl = (const __nv_bfloat16*)(base + S_VL);

        // --- S = Q K^T
        float s[8][4];
#pragma unroll
        for (int nb = 0; nb < 8; nb++)
#pragma unroll
            for (int c = 0; c < 4; c++) s[nb][c] = 0.f;

#pragma unroll
        for (int kb = 0; kb < 6; kb++) {
#pragma unroll
            for (int p = 0; p < 4; p++) {
                int rn = p * 16 + bRow + lrow;
                uint32_t bhv[4], blv[4];
                ldsm4(bhv, sKh + rn * QS + kb * 16 + bCol);
                ldsm4(blv, sKl + rn * QS + kb * 16 + bCol);
                mma_bf16(s[2 * p], qh[kb], bhv[0], bhv[1]);
                mma_bf16(s[2 * p], qh[kb], blv[0], blv[1]);
                mma_bf16(s[2 * p], ql[kb], bhv[0], bhv[1]);
                mma_bf16(s[2 * p + 1], qh[kb], bhv[2], bhv[3]);
                mma_bf16(s[2 * p + 1], qh[kb], blv[2], blv[3]);
                mma_bf16(s[2 * p + 1], ql[kb], bhv[2], bhv[3]);
            }
        }

        // --- online softmax
        float mx0 = -1e30f, mx1 = -1e30f;
#pragma unroll
        for (int nb = 0; nb < 8; nb++) {
            mx0 = fmaxf(mx0, fmaxf(s[nb][0], s[nb][1]));
            mx1 = fmaxf(mx1, fmaxf(s[nb][2], s[nb][3]));
        }
        mx0 = fmaxf(mx0, __shfl_xor_sync(0xffffffffu, mx0, 1));
        mx0 = fmaxf(mx0, __shfl_xor_sync(0xffffffffu, mx0, 2));
        mx1 = fmaxf(mx1, __shfl_xor_sync(0xffffffffu, mx1, 1));
        mx1 = fmaxf(mx1, __shfl_xor_sync(0xffffffffu, mx1, 2));

        float nm0 = fmaxf(m0, mx0), nm1 = fmaxf(m1, mx1);
        float sc0 = __expf(m0 - nm0), sc1 = __expf(m1 - nm1);
        float rs0 = 0.f, rs1 = 0.f;
#pragma unroll
        for (int nb = 0; nb < 8; nb++) {
            s[nb][0] = __expf(s[nb][0] - nm0);
            s[nb][1] = __expf(s[nb][1] - nm0);
            s[nb][2] = __expf(s[nb][2] - nm1);
            s[nb][3] = __expf(s[nb][3] - nm1);
            rs0 += s[nb][0] + s[nb][1];
            rs1 += s[nb][2] + s[nb][3];
        }
        rs0 += __shfl_xor_sync(0xffffffffu, rs0, 1);
        rs0 += __shfl_xor_sync(0xffffffffu, rs0, 2);
        rs1 += __shfl_xor_sync(0xffffffffu, rs1, 1);
        rs1 += __shfl_xor_sync(0xffffffffu, rs1, 2);
        l0 = l0 * sc0 + rs0;
        l1 = l1 * sc1 + rs1;
        m0 = nm0;
        m1 = nm1;
#pragma unroll
        for (int nbd = 0; nbd < 12; nbd++) {
            o[nbd][0] *= sc0;
            o[nbd][1] *= sc0;
            o[nbd][2] *= sc1;
            o[nbd][3] *= sc1;
        }

        // --- O += P V
#pragma unroll
        for (int kb = 0; kb < 4; kb++) {
            float a0 = s[2 * kb][0], a1 = s[2 * kb][1];
            float a2 = s[2 * kb][2], a3 = s[2 * kb][3];
            float b0 = s[2 * kb + 1][0], b1 = s[2 * kb + 1][1];
            float b2 = s[2 * kb + 1][2], b3 = s[2 * kb + 1][3];
            uint32_t PH[4], PL[4];
            PH[0] = pk(a0, a1); PH[1] = pk(a2, a3);
            PH[2] = pk(b0, b1); PH[3] = pk(b2, b3);
            PL[0] = pk(a0 - rb(a0), a1 - rb(a1));
            PL[1] = pk(a2 - rb(a2), a3 - rb(a3));
            PL[2] = pk(b0 - rb(b0), b1 - rb(b1));
            PL[3] = pk(b2 - rb(b2), b3 - rb(b3));
#pragma unroll
            for (int p = 0; p < 6; p++) {
                int rn = p * 16 + bRow + lrow;
                uint32_t vhv[4], vlv[4];
                ldsm4(vhv, sVh + rn * VS + kb * 16 + bCol);
                ldsm4(vlv, sVl + rn * VS + kb * 16 + bCol);
                mma_bf16(o[2 * p], PH, vhv[0], vhv[1]);
                mma_bf16(o[2 * p], PH, vlv[0], vlv[1]);
                mma_bf16(o[2 * p], PL, vhv[0], vhv[1]);
                mma_bf16(o[2 * p + 1], PH, vhv[2], vhv[3]);
                mma_bf16(o[2 * p + 1], PH, vlv[2], vlv[3]);
                mma_bf16(o[2 * p + 1], PL, vhv[2], vhv[3]);
            }
        }
    }

    // --- epilogue
    const float isq = 0.1020620726159657f;   // 1/sqrt(96)
    float iv0 = isq / l0, iv1 = isq / l1;
    int b = bh >> 3, h = bh & 7;
    int r0 = q0 + warp * 16 + g;
    size_t row0 = (size_t)b * Nseq + r0;
    size_t row1 = row0 + 8;
#pragma unroll
    for (int nbd = 0; nbd < 12; nbd++) {
        int e = h * Dh + nbd * 8 + 2 * t;
        splitstore(Oh, Ol, row0 * Emb + e, o[nbd][0] * iv0);
        splitstore(Oh, Ol, row0 * Emb + e + 1, o[nbd][1] * iv0);
        splitstore(Oh, Ol, row1 * Emb + e, o[nbd][2] * iv1);
        splitstore(Oh, Ol, row1 * Emb + e + 1, o[nbd][3] * iv1);
    }
}

// ---------------------------------------------------------------------------
extern "C" void kernel_launch(void* const* d_in, const int* in_sizes, int n_in,
                              void* d_out, int out_size)
{
    const float* x  = (const float*)d_in[0];
    const float* Wq = (const float*)d_in[1];
    const float* bq = (const float*)d_in[2];
    const float* Wk = (const float*)d_in[3];
    const float* bk = (const float*)d_in[4];
    const float* Wv = (const float*)d_in[5];
    const float* bv = (const float*)d_in[6];
    const float* Wo = (const float*)d_in[7];
    const float* bo = (const float*)d_in[8];
    float* out = (float*)d_out;

    __nv_bfloat16 *xh, *xl, *wh, *wl, *qh, *ql, *kh, *kl, *vh, *vl, *ah, *al;
    cudaGetSymbolAddress((void**)&xh, g_xh);
    cudaGetSymbolAddress((void**)&xl, g_xl);
    cudaGetSymbolAddress((void**)&wh, g_wh);
    cudaGetSymbolAddress((void**)&wl, g_wl);
    cudaGetSymbolAddress((void**)&qh, g_qh);
    cudaGetSymbolAddress((void**)&ql, g_ql);
    cudaGetSymbolAddress((void**)&kh, g_kh);
    cudaGetSymbolAddress((void**)&kl, g_kl);
    cudaGetSymbolAddress((void**)&vh, g_vh);
    cudaGetSymbolAddress((void**)&vl, g_vl);
    cudaGetSymbolAddress((void**)&ah, g_ah);
    cudaGetSymbolAddress((void**)&al, g_al);

    cudaFuncSetAttribute(attn_mma_kernel,
                         cudaFuncAttributeMaxDynamicSharedMemorySize, ATTN_SMEM);
    cudaFuncSetAttribute(gemm_mma_kernel,
                         cudaFuncAttributeMaxDynamicSharedMemorySize, GEMM_SMEM);

    conv_split_kernel<<<(Mrows * Emb / 4 + 255) / 256, 256>>>(
        (const float4*)x, (uint2*)xh, (uint2*)xl, Mrows * Emb / 4);
    dim3 wg(Emb / 32, Emb / 32, 4);
    conv_w_kernel<<<wg, dim3(32, 8)>>>(Wq, Wk, Wv, Wo, wh, wl);

    dim3 gg(Emb / 64, Mrows / 128);   // (12, 64)
    gemm_mma_kernel<<<gg, 256, GEMM_SMEM>>>(xh, xl, wh + 0 * (size_t)Emb * Emb, wl + 0 * (size_t)Emb * Emb,
                                            bq, 1, nullptr, qh, ql);
    gemm_mma_kernel<<<gg, 256, GEMM_SMEM>>>(xh, xl, wh + 1 * (size_t)Emb * Emb, wl + 1 * (size_t)Emb * Emb,
                                            bk, 1, nullptr, kh, kl);
    gemm_mma_kernel<<<gg, 256, GEMM_SMEM>>>(xh, xl, wh + 2 * (size_t)Emb * Emb, wl + 2 * (size_t)Emb * Emb,
                                            bv, 2, nullptr, vh, vl);

    dim3 ag(Nseq / 128, NBH);         // (32, 16)
    attn_mma_kernel<<<ag, 256, ATTN_SMEM>>>(qh, ql, kh, kl, vh, vl, ah, al);

    gemm_mma_kernel<<<gg, 256, GEMM_SMEM>>>(ah, al, wh + 3 * (size_t)Emb * Emb, wl + 3 * (size_t)Emb * Emb,
                                            bo, 0, out, nullptr, nullptr);
}